// round 11
// baseline (speedup 1.0000x reference)
#include <cuda_runtime.h>
#include <cuda_bf16.h>
#include <limits.h>

#define H_HALF 4096
#define BLOCK 256
#define NWARP 8            // warps per block = rows per block
#define ITERS 32           // 32 float4 per lane per row: 32*32*4 = 4096 elements
#define THRESH 0.01f
#define MAX_ROWS 8192

__device__ float g_partial[MAX_ROWS];
__device__ unsigned int g_counter = 0;

__global__ __launch_bounds__(BLOCK)
void pulse_loss_kernel(const float* __restrict__ pred,
                       const float* __restrict__ lab,
                       float* __restrict__ out,
                       float scale, int total_rows) {
    const int t = threadIdx.x;
    const int lane = t & 31;
    const int warp = t >> 5;
    const long row = (long)blockIdx.x * NWARP + warp;

    __shared__ int s_is_last;
    __shared__ float s_sum[NWARP];

    if (row < total_rows) {
        const float4* __restrict__ l4 = (const float4*)(lab  + row * H_HALF);
        const float4* __restrict__ p4 = (const float4*)(pred + row * H_HALF);

        // Main streaming pass: per-lane quad sums + quad-granular first/last.
        float s[ITERS];
        int gmin = INT_MAX;
        int gmax = -1;
        #pragma unroll
        for (int i = 0; i < ITERS; i++) {
            const float4 l = __ldcs(&l4[i * 32 + lane]);
            const float4 p = __ldcs(&p4[i * 32 + lane]);
            const float d0 = p.x - l.x, d1 = p.y - l.y;
            const float d2 = p.z - l.z, d3 = p.w - l.w;
            s[i] = d0 * d0 + d1 * d1 + d2 * d2 + d3 * d3;
            const float m = fmaxf(fmaxf(fabsf(l.x), fabsf(l.y)),
                                  fmaxf(fabsf(l.z), fabsf(l.w)));
            const int g = i * 128 + lane * 4;   // quad start (global element idx)
            if (m > THRESH) { gmin = min(gmin, g); gmax = max(gmax, g); }
        }

        // Quad-level first/last across warp (no smem, no block barrier)
        const int qf = __reduce_min_sync(0xFFFFFFFFu, gmin);
        const int ql = __reduce_max_sync(0xFFFFFFFFu, gmax);

        int first, last;
        float corr = 0.0f;   // warp-uniform boundary-quad correction
        if (qf == INT_MAX) {
            // all-insignificant row: argmax fallback -> no outside region
            first = 0;
            last = H_HALF - 1;
        } else {
            {   // refine first within its quad (uniform 16B reload, L2-hot)
                const float4 l = l4[qf >> 2];
                int off = 3;
                if (fabsf(l.z) > THRESH) off = 2;
                if (fabsf(l.y) > THRESH) off = 1;
                if (fabsf(l.x) > THRESH) off = 0;
                first = qf + off;
            }
            {   // refine last within its quad
                const float4 l = l4[ql >> 2];
                int off = 0;
                if (fabsf(l.y) > THRESH) off = 1;
                if (fabsf(l.z) > THRESH) off = 2;
                if (fabsf(l.w) > THRESH) off = 3;
                last = ql + off;
            }
            // Boundary-quad partial-outside corrections (extra 1x weight for
            // elements before first / after last inside their own quads).
            const int fr = first & 3;
            if (fr != 0) {
                const float4 l = l4[first >> 2];
                const float4 p = p4[first >> 2];
                const float d0 = p.x - l.x, d1 = p.y - l.y, d2 = p.z - l.z;
                if (fr > 0) corr += d0 * d0;
                if (fr > 1) corr += d1 * d1;
                if (fr > 2) corr += d2 * d2;
            }
            const int lr = last & 3;
            if (lr != 3) {
                const float4 l = l4[last >> 2];
                const float4 p = p4[last >> 2];
                const float d1 = p.y - l.y, d2 = p.z - l.z, d3 = p.w - l.w;
                if (lr < 1) corr += d1 * d1;
                if (lr < 2) corr += d2 * d2;
                if (lr < 3) corr += d3 * d3;
            }
        }

        // Branch-free weighted scan: weight 2 for fully-outside quads,
        // weight 1 otherwise (boundary quads get their extra via corr).
        float acc = 0.0f;
        #pragma unroll
        for (int i = 0; i < ITERS; i++) {
            const int g = i * 128 + lane * 4;
            const bool fully_out = (g + 3 < first) || (g > last);
            acc += fully_out ? (s[i] + s[i]) : s[i];
        }

        // Warp reduce (deterministic), lane 0 writes the row partial
        #pragma unroll
        for (int o = 16; o > 0; o >>= 1)
            acc += __shfl_xor_sync(0xFFFFFFFFu, acc, o);
        if (lane == 0) {
            g_partial[row] = acc + corr;
            __threadfence();   // writer-side release before the block signals
        }
    }

    __syncthreads();
    if (t == 0) {
        unsigned int done = atomicAdd(&g_counter, 1u);
        s_is_last = (done == gridDim.x - 1) ? 1 : 0;
    }
    __syncthreads();

    // Last block: deterministic final reduction over all row partials
    if (s_is_last) {
        __threadfence();
        float facc = 0.0f;
        for (int i = t; i < total_rows; i += BLOCK)
            facc += __ldcg(&g_partial[i]);   // fixed order -> deterministic
        #pragma unroll
        for (int o = 16; o > 0; o >>= 1)
            facc += __shfl_xor_sync(0xFFFFFFFFu, facc, o);
        if (lane == 0) s_sum[warp] = facc;
        __syncthreads();
        if (t == 0) {
            float v = 0.0f;
            #pragma unroll
            for (int w = 0; w < NWARP; w++) v += s_sum[w];
            out[0] = v * scale;
            g_counter = 0;   // reset for next graph replay
        }
    }
}

extern "C" void kernel_launch(void* const* d_in, const int* in_sizes, int n_in,
                              void* d_out, int out_size) {
    const float* pred = (const float*)d_in[0];
    const float* lab  = (const float*)d_in[1];
    float* out = (float*)d_out;

    const long n = in_sizes[0];                 // total elements (B * N)
    const int total_rows = (int)(n / H_HALF);   // B * 2 half-rows
    const long B = total_rows / 2;
    const float scale = 1.0f / ((float)B * (float)H_HALF);

    const unsigned grid = (unsigned)((total_rows + NWARP - 1) / NWARP);
    pulse_loss_kernel<<<grid, BLOCK>>>(pred, lab, out, scale, total_rows);
}

// round 14
// speedup vs baseline: 1.1725x; 1.1725x over previous
#include <cuda_runtime.h>
#include <cuda_bf16.h>
#include <limits.h>
#include <stdint.h>

#define H_HALF 4096
#define BLOCK 256
#define NWARP (BLOCK / 32)
#define V4 4                 // 4 float4 per thread = 16 floats; 256*16 = 4096
#define THRESH 0.01f
#define MAX_ROWS 8192

__device__ float g_partial[MAX_ROWS];
__device__ unsigned int g_counter = 0;

__device__ __forceinline__ uint32_t smem_u32(const void* p) {
    uint32_t a;
    asm("{ .reg .u64 tmp; cvta.to.shared.u64 tmp, %1; cvt.u32.u64 %0, tmp; }"
        : "=r"(a) : "l"(p));
    return a;
}

__device__ __forceinline__ void cp_async16(uint32_t dst_smem, const void* src) {
    asm volatile("cp.async.cg.shared.global [%0], [%1], 16;"
                 :: "r"(dst_smem), "l"(src) : "memory");
}

__global__ __launch_bounds__(BLOCK, 8)
void pulse_loss_kernel(const float* __restrict__ pred,
                       const float* __restrict__ lab,
                       float* __restrict__ out,
                       float scale, int total_rows) {
    __shared__ float lab_s[H_HALF];          // 16 KB staged labels
    __shared__ int s_first, s_last;
    __shared__ float s_sum[NWARP];
    __shared__ int s_is_last;

    const int t = threadIdx.x;
    const int wid = t >> 5;
    const int lid = t & 31;
    const long row = blockIdx.x;

    const float4* __restrict__ l4 = (const float4*)(lab  + row * H_HALF);
    const float4* __restrict__ p4 = (const float4*)(pred + row * H_HALF);
    const uint32_t lab_s_base = smem_u32(lab_s);

    if (t == 0) { s_first = INT_MAX; s_last = -1; }

    // Labels -> SMEM via cp.async (no register cost for in-flight data)
    #pragma unroll
    for (int i = 0; i < V4; i++) {
        const int v = t + i * BLOCK;
        cp_async16(lab_s_base + v * 16, &l4[v]);
    }
    asm volatile("cp.async.commit_group;" ::: "memory");

    // Pred -> registers (front-batched, stays in flight across mask phase)
    float4 p[V4];
    #pragma unroll
    for (int i = 0; i < V4; i++)
        p[i] = __ldcs(&p4[t + i * BLOCK]);

    __syncthreads();   // orders s_first/s_last init before atomics below

    // Wait for OWN label copies (each thread reads only indices it copied),
    // then compute element-level first/last from SMEM.
    asm volatile("cp.async.wait_group 0;" ::: "memory");

    int firstI = INT_MAX;
    int lastI  = -1;
    #pragma unroll
    for (int i = 0; i < V4; i++) {
        const int v = t + i * BLOCK;
        const float4 l = *(const float4*)(lab_s + v * 4);
        const int gi = v * 4;
        if (fabsf(l.x) > THRESH) { firstI = min(firstI, gi + 0); lastI = max(lastI, gi + 0); }
        if (fabsf(l.y) > THRESH) { firstI = min(firstI, gi + 1); lastI = max(lastI, gi + 1); }
        if (fabsf(l.z) > THRESH) { firstI = min(firstI, gi + 2); lastI = max(lastI, gi + 2); }
        if (fabsf(l.w) > THRESH) { firstI = min(firstI, gi + 3); lastI = max(lastI, gi + 3); }
    }
    const int wf = __reduce_min_sync(0xFFFFFFFFu, firstI);
    const int wl = __reduce_max_sync(0xFFFFFFFFu, lastI);
    if (lid == 0) {
        atomicMin(&s_first, wf);   // order-independent -> deterministic
        atomicMax(&s_last, wl);
    }
    __syncthreads();

    int first = s_first;
    int last  = s_last;
    if (first == INT_MAX) { first = 0; last = H_HALF - 1; }   // all-insignificant fallback

    // Weighted squared diffs: labels re-read from SMEM, preds from registers
    float acc = 0.0f;
    #pragma unroll
    for (int i = 0; i < V4; i++) {
        const int v = t + i * BLOCK;
        const float4 l = *(const float4*)(lab_s + v * 4);
        const int gi = v * 4;
        const float d0 = p[i].x - l.x;
        const float d1 = p[i].y - l.y;
        const float d2 = p[i].z - l.z;
        const float d3 = p[i].w - l.w;
        const float w0 = (gi + 0 < first || gi + 0 > last) ? 2.0f : 1.0f;
        const float w1 = (gi + 1 < first || gi + 1 > last) ? 2.0f : 1.0f;
        const float w2 = (gi + 2 < first || gi + 2 > last) ? 2.0f : 1.0f;
        const float w3 = (gi + 3 < first || gi + 3 > last) ? 2.0f : 1.0f;
        acc += w0 * d0 * d0 + w1 * d1 * d1 + w2 * d2 * d2 + w3 * d3 * d3;
    }

    // Block reduce sum (deterministic)
    #pragma unroll
    for (int o = 16; o > 0; o >>= 1)
        acc += __shfl_xor_sync(0xFFFFFFFFu, acc, o);
    if (lid == 0) s_sum[wid] = acc;
    __syncthreads();
    if (t == 0) {
        float v = 0.0f;
        #pragma unroll
        for (int w = 0; w < NWARP; w++) v += s_sum[w];
        g_partial[row] = v;
        __threadfence();
        unsigned int done = atomicAdd(&g_counter, 1u);
        s_is_last = (done == gridDim.x - 1) ? 1 : 0;
    }
    __syncthreads();

    // Last block: deterministic final reduction over all row partials
    if (s_is_last) {
        __threadfence();
        float facc = 0.0f;
        for (int i = t; i < total_rows; i += BLOCK)
            facc += __ldcg(&g_partial[i]);   // fixed order -> deterministic
        #pragma unroll
        for (int o = 16; o > 0; o >>= 1)
            facc += __shfl_xor_sync(0xFFFFFFFFu, facc, o);
        if (lid == 0) s_sum[wid] = facc;
        __syncthreads();
        if (t == 0) {
            float v = 0.0f;
            #pragma unroll
            for (int w = 0; w < NWARP; w++) v += s_sum[w];
            out[0] = v * scale;
            g_counter = 0;   // reset for next graph replay
        }
    }
}

extern "C" void kernel_launch(void* const* d_in, const int* in_sizes, int n_in,
                              void* d_out, int out_size) {
    const float* pred = (const float*)d_in[0];
    const float* lab  = (const float*)d_in[1];
    float* out = (float*)d_out;

    const long n = in_sizes[0];                 // total elements (B * N)
    const int total_rows = (int)(n / H_HALF);   // B * 2 half-rows
    const long B = total_rows / 2;
    const float scale = 1.0f / ((float)B * (float)H_HALF);

    pulse_loss_kernel<<<(unsigned)total_rows, BLOCK>>>(pred, lab, out, scale, total_rows);
}